// round 2
// baseline (speedup 1.0000x reference)
#include <cuda_runtime.h>
#include <math.h>

#define FDIM 256
#define BMAX 1024
#define NMAX 1048576

// ---------------- scratch (static device globals; no allocation) ----------------
__device__ __align__(128) float g_h0k[BMAX * FDIM];
__device__ __align__(128) float g_h0v[BMAX * FDIM];
__device__ __align__(128) float g_ak [BMAX * FDIM];
__device__ __align__(128) float g_av [BMAX * FDIM];
__device__ __align__(128) float g_t1k[BMAX * FDIM];
__device__ __align__(128) float g_t1v[BMAX * FDIM];
__device__ __align__(128) float g_rk [BMAX * FDIM];
__device__ __align__(128) float g_rv [BMAX * FDIM];
__device__ __align__(128) float g_km [BMAX * FDIM];
__device__ __align__(128) float g_vm [BMAX * FDIM];
__device__ __align__(128) float g_kq [BMAX * FDIM];
__device__ __align__(128) float g_dot[NMAX];
__device__ __align__(128) int   g_seg[NMAX];
__device__ __align__(128) float g_smax[BMAX];
__device__ __align__(128) float g_inv [BMAX];

__device__ __forceinline__ float actf(float x) {
    // x * sigmoid(1.702 x)
    return x / (1.0f + expf(-1.702f * x));
}

// ---------------- kernel 0: normalize batch_seg to int32 ----------------
// The reference claims int64 but JAX (x64 disabled) materializes int32.
// Detect on-device: data is sorted with max = B-1 > 0. If the buffer is
// int64 (little-endian, values < 2^31), the int32 view at position N-1 is
// the HIGH word of element (N-1)/2, i.e. 0. If the buffer is int32, the
// value at N-1 is the max segment id (>0). Branch accordingly.
__global__ void segconv_kernel(const int* __restrict__ seg32, int N) {
    int i = blockIdx.x * blockDim.x + threadIdx.x;
    if (i >= N) return;
    bool is64 = (seg32[N - 1] == 0);
    g_seg[i] = is64 ? seg32[2 * i] : seg32[i];
}

// ---------------- kernel 1: entry embeddings ----------------
// h0k[b,f] = E[b]*Wkf[f] + bkf[f]; h0v[b,f] = E[b]*Wvf[f]; plus act() of each.
__global__ void entry_kernel(const float* __restrict__ E,
                             const float* __restrict__ Wkf,
                             const float* __restrict__ bkf,
                             const float* __restrict__ Wvf,
                             int B) {
    int idx = blockIdx.x * blockDim.x + threadIdx.x;
    if (idx >= B * FDIM) return;
    int b = idx >> 8;
    int f = idx & 255;
    float e = E[b];
    float hk = e * Wkf[f] + bkf[f];
    float hv = e * Wvf[f];
    g_h0k[idx] = hk;
    g_ak[idx]  = actf(hk);
    g_h0v[idx] = hv;
    g_av[idx]  = actf(hv);
}

// ---------------- kernel 2: generic small-GEMM layer ----------------
// wTransposed=1 : C = A @ W^T (+bias)(+R)(act?)   W row-major FDIM x FDIM
// wTransposed=0 : C = A @ W   (+bias)(+R)(act?)
// gridDim.y selects branch (0=k set, 1=v set). BM=32 rows, BN=64 outputs per block.
__global__ __launch_bounds__(256)
void layer_kernel(const float* __restrict__ A0, const float* __restrict__ A1,
                  const float* __restrict__ W0, const float* __restrict__ W1,
                  const float* __restrict__ b0, const float* __restrict__ b1,
                  const float* __restrict__ R0, const float* __restrict__ R1,
                  float* __restrict__ C0, float* __restrict__ C1,
                  int M, int applyAct, int wTransposed) {
    extern __shared__ float sm[];
    float* As = sm;                 // 32 x 256
    float* Ws = sm + 32 * 256;      // 64 x 260 (padded rows)

    const float* A    = blockIdx.y ? A1 : A0;
    const float* W    = blockIdx.y ? W1 : W0;
    const float* bias = blockIdx.y ? b1 : b0;
    const float* R    = blockIdx.y ? R1 : R0;
    float*       C    = blockIdx.y ? C1 : C0;

    int t = threadIdx.x;
    int fTile = blockIdx.x & 3;
    int row0  = (blockIdx.x >> 2) * 32;
    int f0    = fTile * 64;

    // load A tile (32 x 256), coalesced float4
    const float4* A4 = (const float4*)A;
    #pragma unroll
    for (int i = 0; i < 8; i++) {
        int j  = i * 256 + t;        // float4 index within 2048-float4 tile
        int r  = j >> 6;
        int c4 = j & 63;
        float4 v;
        if (row0 + r < M) v = A4[(size_t)(row0 + r) * 64 + c4];
        else              v = make_float4(0.f, 0.f, 0.f, 0.f);
        *(float4*)(As + r * 256 + c4 * 4) = v;
    }

    // load W tile (64 x 256) into padded shared
    if (wTransposed) {
        const float4* W4 = (const float4*)W;
        #pragma unroll
        for (int i = 0; i < 16; i++) {
            int j  = i * 256 + t;    // 4096 float4 total
            int n  = j >> 6;
            int c4 = j & 63;
            float4 v = W4[(size_t)(f0 + n) * 64 + c4];
            *(float4*)(Ws + n * 260 + c4 * 4) = v;
        }
    } else {
        #pragma unroll
        for (int i = 0; i < 64; i++) {
            int j = i * 256 + t;     // 16384 scalars
            int n = j & 63;
            int k = j >> 6;
            Ws[n * 260 + k] = W[(size_t)k * FDIM + f0 + n];
        }
    }
    __syncthreads();

    int f  = t & 63;
    int rg = t >> 6;
    float acc[8];
    #pragma unroll
    for (int r = 0; r < 8; r++) acc[r] = 0.f;

    const float* wrow = Ws + f * 260;
    const float* abase = As + rg * 8 * 256;
    #pragma unroll 4
    for (int g = 0; g < 256; g += 4) {
        float4 w = *(const float4*)(wrow + g);
        #pragma unroll
        for (int r = 0; r < 8; r++) {
            float4 a = *(const float4*)(abase + r * 256 + g);
            acc[r] += a.x * w.x + a.y * w.y + a.z * w.z + a.w * w.w;
        }
    }

    float bb = bias ? bias[f0 + f] : 0.f;
    #pragma unroll
    for (int r = 0; r < 8; r++) {
        int row = row0 + rg * 8 + r;
        if (row < M) {
            float v = acc[r] + bb;
            if (R) v += R[(size_t)row * FDIM + f0 + f];
            if (applyAct) v = actf(v);
            C[(size_t)row * FDIM + f0 + f] = v;
        }
    }
}

// ---------------- kernel 3: dot pass ----------------
// dot[i] = x[i,:] . kq[seg[i],:]   (one warp per row)
__global__ void dot_kernel(const float4* __restrict__ x,
                           const float* __restrict__ kq,
                           float* __restrict__ dotv,
                           int N) {
    int gw   = (blockIdx.x * blockDim.x + threadIdx.x) >> 5;
    int lane = threadIdx.x & 31;
    if (gw >= N) return;
    int b = g_seg[gw];
    const float4* xr = x + (size_t)gw * 64;
    const float4* kr = (const float4*)kq + (size_t)b * 64;

    float4 a0 = xr[lane];
    float4 k0 = kr[lane];
    float4 a1 = xr[lane + 32];
    float4 k1 = kr[lane + 32];
    float s = a0.x * k0.x + a0.y * k0.y + a0.z * k0.z + a0.w * k0.w
            + a1.x * k1.x + a1.y * k1.y + a1.z * k1.z + a1.w * k1.w;
    #pragma unroll
    for (int o = 16; o; o >>= 1) s += __shfl_xor_sync(0xffffffffu, s, o);
    if (lane == 0) dotv[gw] = s;
}

// ---------------- kernel 4: deterministic segment reduce ----------------
// g_seg is sorted -> segment b is the contiguous range [lb(b), lb(b+1)).
// One block per segment: pass1 max, pass2 sum of exp((dot-max)*scale).
__device__ __forceinline__ int lowerb(const int* __restrict__ s, int n, int v) {
    int lo = 0, hi = n;
    while (lo < hi) {
        int mid = (lo + hi) >> 1;
        if (s[mid] < v) lo = mid + 1; else hi = mid;
    }
    return lo;
}

__global__ void segreduce_kernel(const float* __restrict__ dotv,
                                 float* __restrict__ smax,
                                 float* __restrict__ invnorm,
                                 int N, float scale) {
    __shared__ float red[256];
    __shared__ int sse[2];
    int b = blockIdx.x;
    int t = threadIdx.x;
    if (t == 0) {
        sse[0] = lowerb(g_seg, N, b);
        sse[1] = lowerb(g_seg, N, b + 1);
    }
    __syncthreads();
    int start = sse[0], end = sse[1];

    float m = -3.4e38f;
    for (int i = start + t; i < end; i += 256) m = fmaxf(m, dotv[i]);
    red[t] = m;
    __syncthreads();
    #pragma unroll
    for (int s = 128; s; s >>= 1) {
        if (t < s) red[t] = fmaxf(red[t], red[t + s]);
        __syncthreads();
    }
    float mx = red[0];
    __syncthreads();

    float ss = 0.f;
    for (int i = start + t; i < end; i += 256) ss += expf((dotv[i] - mx) * scale);
    red[t] = ss;
    __syncthreads();
    #pragma unroll
    for (int s = 128; s; s >>= 1) {
        if (t < s) red[t] += red[t + s];
        __syncthreads();
    }
    if (t == 0) {
        smax[b] = mx;
        invnorm[b] = 1.f / (red[0] + 1e-8f);
    }
}

// ---------------- kernel 5: output ----------------
// out[i,:] = exp((dot[i]-smax[seg])*scale) * inv[seg] * v_mol[seg,:]
__global__ void out_kernel(const float* __restrict__ dotv,
                           const float* __restrict__ vm,
                           const float* __restrict__ smax,
                           const float* __restrict__ invnorm,
                           float4* __restrict__ out,
                           int N, float scale) {
    int gw   = (blockIdx.x * blockDim.x + threadIdx.x) >> 5;
    int lane = threadIdx.x & 31;
    if (gw >= N) return;
    int b = g_seg[gw];
    float coef = expf((dotv[gw] - smax[b]) * scale) * invnorm[b];
    const float4* vr = (const float4*)vm + (size_t)b * 64;
    float4* orow = out + (size_t)gw * 64;

    float4 v0 = vr[lane];
    v0.x *= coef; v0.y *= coef; v0.z *= coef; v0.w *= coef;
    orow[lane] = v0;
    float4 v1 = vr[lane + 32];
    v1.x *= coef; v1.y *= coef; v1.z *= coef; v1.w *= coef;
    orow[lane + 32] = v1;
}

// ---------------- launcher ----------------
extern "C" void kernel_launch(void* const* d_in, const int* in_sizes, int n_in,
                              void* d_out, int out_size) {
    // input order (17 inputs): x, E, num_batch, batch_seg, Wq, Wkf, bkf, Wvf,
    //                          kW1, kb1, kW2, kb2, kWo, kbo, vW1, vW2, vWo
    // If the scalar num_batch was dropped (16 inputs), everything after E
    // shifts down by one.
    int sh = (n_in >= 17) ? 0 : 1;   // shift to subtract for indices >= 2
    const float* x    = (const float*)d_in[0];
    const float* E    = (const float*)d_in[1];
    const int*   seg  = (const int*)  d_in[3 - sh];
    const float* Wq   = (const float*)d_in[4 - sh];
    const float* Wkf  = (const float*)d_in[5 - sh];
    const float* bkf  = (const float*)d_in[6 - sh];
    const float* Wvf  = (const float*)d_in[7 - sh];
    const float* kW1  = (const float*)d_in[8 - sh];
    const float* kb1  = (const float*)d_in[9 - sh];
    const float* kW2  = (const float*)d_in[10 - sh];
    const float* kb2  = (const float*)d_in[11 - sh];
    const float* kWo  = (const float*)d_in[12 - sh];
    const float* kbo  = (const float*)d_in[13 - sh];
    const float* vW1  = (const float*)d_in[14 - sh];
    const float* vW2  = (const float*)d_in[15 - sh];
    const float* vWo  = (const float*)d_in[16 - sh];

    int B = in_sizes[1];        // E has B elements
    int N = in_sizes[3 - sh];   // batch_seg has N elements
    float scale = 1.f / sqrtf((float)FDIM);

    float *h0k, *h0v, *ak, *av, *t1k, *t1v, *rk, *rv, *km, *vm, *kq, *dotv, *smax, *inv;
    cudaGetSymbolAddress((void**)&h0k, g_h0k);
    cudaGetSymbolAddress((void**)&h0v, g_h0v);
    cudaGetSymbolAddress((void**)&ak,  g_ak);
    cudaGetSymbolAddress((void**)&av,  g_av);
    cudaGetSymbolAddress((void**)&t1k, g_t1k);
    cudaGetSymbolAddress((void**)&t1v, g_t1v);
    cudaGetSymbolAddress((void**)&rk,  g_rk);
    cudaGetSymbolAddress((void**)&rv,  g_rv);
    cudaGetSymbolAddress((void**)&km,  g_km);
    cudaGetSymbolAddress((void**)&vm,  g_vm);
    cudaGetSymbolAddress((void**)&kq,  g_kq);
    cudaGetSymbolAddress((void**)&dotv, g_dot);
    cudaGetSymbolAddress((void**)&smax, g_smax);
    cudaGetSymbolAddress((void**)&inv,  g_inv);

    const int SMEM = (32 * 256 + 64 * 260) * (int)sizeof(float);  // 99328 B
    cudaFuncSetAttribute(layer_kernel, cudaFuncAttributeMaxDynamicSharedMemorySize, SMEM);

    // 0) normalize batch_seg (int32 vs int64 robust)
    segconv_kernel<<<(N + 255) / 256, 256>>>(seg, N);

    // 1) entry
    entry_kernel<<<(B * FDIM + 255) / 256, 256>>>(E, Wkf, bkf, Wvf, B);

    // 2) resMLP layers (k and v branches in one launch via gridDim.y)
    int tilesM = (B + 31) / 32;
    dim3 lgrid(tilesM * 4, 2);
    // t1 = act(act(h0) @ W1^T + b1)
    layer_kernel<<<lgrid, 256, SMEM>>>(ak, av, kW1, vW1, kb1, nullptr,
                                       nullptr, nullptr, t1k, t1v, B, 1, 1);
    // actr = act(h0 + t1 @ W2^T + b2)
    layer_kernel<<<lgrid, 256, SMEM>>>(t1k, t1v, kW2, vW2, kb2, nullptr,
                                       h0k, h0v, rk, rv, B, 1, 1);
    // mol = actr @ Wo^T + bo
    layer_kernel<<<lgrid, 256, SMEM>>>(rk, rv, kWo, vWo, kbo, nullptr,
                                       nullptr, nullptr, km, vm, B, 0, 1);
    // kq = k_mol @ Wq   (note: NOT transposed)
    dim3 qgrid(tilesM * 4, 1);
    layer_kernel<<<qgrid, 256, SMEM>>>(km, km, Wq, Wq, nullptr, nullptr,
                                       nullptr, nullptr, kq, kq, B, 0, 0);

    // 3) dot pass (one warp per row)
    int nwb = (N * 32 + 255) / 256;
    dot_kernel<<<nwb, 256>>>((const float4*)x, kq, dotv, N);

    // 4) deterministic per-segment max + expsum
    segreduce_kernel<<<B, 256>>>(dotv, smax, inv, N, scale);

    // 5) output pass
    out_kernel<<<nwb, 256>>>(dotv, vm, smax, inv, (float4*)d_out, N, scale);
}